// round 12
// baseline (speedup 1.0000x reference)
#include <cuda_runtime.h>
#include <cuda_bf16.h>
#include <stdint.h>
#include <math.h>

#define B_   32
#define C_   256
#define HH   56
#define WW   56
#define E_   4
#define O_   256
#define HID_ 64
#define NPIX 3136
#define KDIM 2304
#define WPERB (O_*KDIM)
#define BK   32
#define NKT  (KDIM/BK)                // 72 k-tiles
#define PADK 36                       // smem k-stride (floats)
#define PIMG 3364                     // 58*58 padded plane
#define BN   384                      // CTA n tile
#define NTILES 9                      // ceil(3136/384)
#define ASTG (128*PADK)               // 4608 floats per A stage
#define BSTG (BN*PADK)                // 13824 floats per B stage
// smem float offsets
#define BOFF (2*ASTG)                 // 9216
#define KOFF (BOFF + 3*BSTG)          // 9216 + 41472 = 50688
#define CONV_SMEM ((KOFF + KDIM)*4)   // 52992*4 = 211968 B

// ---------------- device scratch (no runtime allocation) ----------------
__device__ float g_routing[B_*E_];
__device__ float g_pooled[B_*C_];
__device__ float g_combined[(size_t)B_*WPERB];        // tf32-rounded mixed weights
__device__ __align__(16) float g_xpad[(size_t)B_*C_*PIMG + 4096]; // padded tf32 x

// ---------------- helpers ----------------
__device__ __forceinline__ uint32_t f2tf32(float f) {
    uint32_t u;
    asm("cvt.rna.tf32.f32 %0, %1;" : "=r"(u) : "f"(f));
    return u;
}

__device__ __forceinline__ void mma_tf32(float* d, const uint32_t* a, uint32_t b0, uint32_t b1) {
    asm volatile(
        "mma.sync.aligned.m16n8k8.row.col.f32.tf32.tf32.f32 "
        "{%0,%1,%2,%3}, {%4,%5,%6,%7}, {%8,%9}, {%0,%1,%2,%3};"
        : "+f"(d[0]), "+f"(d[1]), "+f"(d[2]), "+f"(d[3])
        : "r"(a[0]), "r"(a[1]), "r"(a[2]), "r"(a[3]), "r"(b0), "r"(b1));
}

#define CP_ASYNC16(dst_u32, src_ptr) \
    asm volatile("cp.async.cg.shared.global [%0], [%1], 16;" :: "r"(dst_u32), "l"(src_ptr))
#define CP_COMMIT() asm volatile("cp.async.commit_group;" ::: "memory")
#define CP_WAIT0()  asm volatile("cp.async.wait_group 0;"  ::: "memory")

// ===========================================================================
// Kernel 1a: fused zero-pad + tf32-round + global average pool.
// ===========================================================================
__global__ void __launch_bounds__(128) pad_pool_kernel(const float* __restrict__ x) {
    const int c = blockIdx.x, b = blockIdx.y;
    const int tid = threadIdx.x;
    const float* src = x + ((size_t)b*C_ + c)*NPIX;
    float* dst = g_xpad + ((size_t)b*C_ + c)*PIMG;

    float s = 0.f;
    for (int idx = tid; idx < PIMG; idx += 128) {
        const int py = idx / 58;
        const int px = idx - py*58;
        float v = 0.f;
        if ((unsigned)(py-1) < 56u && (unsigned)(px-1) < 56u) {
            v = src[(py-1)*WW + (px-1)];
            s += v;
        }
        dst[idx] = __uint_as_float(f2tf32(v));
    }
    #pragma unroll
    for (int o = 16; o; o >>= 1) s += __shfl_xor_sync(0xffffffffu, s, o);
    __shared__ float ws[4];
    if ((tid & 31) == 0) ws[tid >> 5] = s;
    __syncthreads();
    if (tid == 0) g_pooled[b*C_ + c] = (ws[0]+ws[1]+ws[2]+ws[3]) * (1.0f/(float)NPIX);
}

// ===========================================================================
// Kernel 1b: MLP + softmax routing. grid B_, 64 threads.
// ===========================================================================
__global__ void __launch_bounds__(64) mlp_kernel(const float* __restrict__ rw1,
                                                 const float* __restrict__ rb1,
                                                 const float* __restrict__ rw2,
                                                 const float* __restrict__ rb2) {
    const int b = blockIdx.x, t = threadIdx.x;
    __shared__ float pl[C_];
    __shared__ float hid[HID_];
    __shared__ float logits[E_];
    for (int c = t; c < C_; c += 64) pl[c] = g_pooled[b*C_ + c];
    __syncthreads();
    {
        float s = rb1[t];
        const float* w = rw1 + t * C_;
        #pragma unroll 8
        for (int c = 0; c < C_; c++) s = fmaf(w[c], pl[c], s);
        hid[t] = fmaxf(s, 0.f);
    }
    __syncthreads();
    if (t < E_) {
        float s = rb2[t];
        const float* w = rw2 + t * HID_;
        #pragma unroll 8
        for (int h = 0; h < HID_; h++) s = fmaf(w[h], hid[h], s);
        logits[t] = s;
    }
    __syncthreads();
    if (t == 0) {
        float m = logits[0];
        #pragma unroll
        for (int e = 1; e < E_; e++) m = fmaxf(m, logits[e]);
        float ex[E_], sum = 0.f;
        #pragma unroll
        for (int e = 0; e < E_; e++) { ex[e] = expf(logits[e] - m); sum += ex[e]; }
        float inv = 1.0f / sum;
        #pragma unroll
        for (int e = 0; e < E_; e++) g_routing[b*E_ + e] = ex[e] * inv;
    }
}

// ===========================================================================
// Kernel 2: mix experts -> per-sample weights (tf32-rounded fp32, flat).
// ===========================================================================
__global__ void __launch_bounds__(256) combine_kernel(const float* __restrict__ experts) {
    const int b = blockIdx.y;
    const int i = blockIdx.x * 256 + threadIdx.x;     // float4 index (exact grid)

    const float r0 = g_routing[b*E_+0], r1 = g_routing[b*E_+1];
    const float r2 = g_routing[b*E_+2], r3 = g_routing[b*E_+3];
    float4 a = ((const float4*)(experts + (size_t)0*WPERB))[i];
    float4 c = ((const float4*)(experts + (size_t)1*WPERB))[i];
    float4 d = ((const float4*)(experts + (size_t)2*WPERB))[i];
    float4 f = ((const float4*)(experts + (size_t)3*WPERB))[i];

    uint4 o;
    o.x = f2tf32(r0*a.x + r1*c.x + r2*d.x + r3*f.x);
    o.y = f2tf32(r0*a.y + r1*c.y + r2*d.y + r3*f.y);
    o.z = f2tf32(r0*a.z + r1*c.z + r2*d.z + r3*f.z);
    o.w = f2tf32(r0*a.w + r1*c.w + r2*d.w + r3*f.w);
    ((uint4*)g_combined)[(size_t)b*(WPERB/4) + i] = o;
}

// ===========================================================================
// Kernel 3: TF32 mma.sync implicit-GEMM conv.
//   CTA 128(oc) x 384(px), 12 warps = 2(m) x 6(n), warp tile 64x64, 1 CTA/SM.
//   A: cp.async double-buffered; B: LDG(g_xpad)->STS.128, 3 stages,
//   quarter-phase staging (8 regs) interleaved with ks compute.
// ===========================================================================
__global__ void __launch_bounds__(384, 1) conv_mma_kernel(float* __restrict__ out) {
    extern __shared__ float sm[];
    float* As   = sm;                          // 2 * ASTG
    float* Bs   = sm + BOFF;                   // 3 * BSTG
    int*   ktab = (int*)(sm + KOFF);

    const int tid    = threadIdx.x;
    const int lane   = tid & 31;
    const int warp   = tid >> 5;
    const int nBase  = blockIdx.x * BN;
    const int tile_m = blockIdx.y;
    const int b      = blockIdx.z;

    const int g  = lane >> 2;      // 0..7
    const int tg = lane & 3;       // 0..3
    const int wm = warp / 6;       // 0..1 (m)
    const int wn = warp % 6;       // 0..5 (n)

    // im2col table: gmem delta into padded planes
    for (int k = tid; k < KDIM; k += 384) {
        int c = k / 9, rem = k - 9*c;
        int ky = rem / 3 - 1, kx = rem % 3 - 1;
        ktab[k] = c*PIMG + ky*58 + kx;
    }
    __syncthreads();

    const float* Ab = g_combined + (size_t)b*WPERB + (size_t)(tile_m*128)*KDIM;

    // B producer: one pixel per thread
    const int n  = nBase + tid;
    const int ny = n / WW, nx = n - (n / WW) * WW;
    const float* xpb = g_xpad + (size_t)b*C_*PIMG + (ny+1)*58 + (nx+1);

    const uint32_t as_u32 = (uint32_t)__cvta_generic_to_shared(As);

    float breg[8];

    // A tile = 1024 float4; threads 0..255 do 3, rest 2
    #define ISSUE_A(kt_, s) do {                                                     \
        const int _k0 = (kt_) * BK;                                                  \
        _Pragma("unroll")                                                            \
        for (int i = 0; i < 3; i++) {                                                \
            int idx = tid + i*384;                                                   \
            if (idx < 1024) {                                                        \
                int row = idx >> 3, c4 = idx & 7;                                    \
                uint32_t dst = as_u32 + (uint32_t)((s)*ASTG + row*PADK + c4*4)*4u;   \
                CP_ASYNC16(dst, Ab + (size_t)row*KDIM + _k0 + c4*4);                 \
            }                                                                        \
        }                                                                            \
        CP_COMMIT();                                                                 \
    } while (0)

    #define LDG_Q(kt_, q) do {                                                       \
        const int4* _t4 = (const int4*)(ktab + (kt_)*BK + (q)*8);                    \
        int4 k0v = _t4[0], k1v = _t4[1];                                             \
        breg[0] = __ldg(xpb + k0v.x);  breg[1] = __ldg(xpb + k0v.y);                 \
        breg[2] = __ldg(xpb + k0v.z);  breg[3] = __ldg(xpb + k0v.w);                 \
        breg[4] = __ldg(xpb + k1v.x);  breg[5] = __ldg(xpb + k1v.y);                 \
        breg[6] = __ldg(xpb + k1v.z);  breg[7] = __ldg(xpb + k1v.w);                 \
    } while (0)

    #define STS_Q(s3, q) do {                                                        \
        float4* _d = (float4*)(Bs + (s3)*BSTG + tid*PADK + (q)*8);                   \
        _d[0] = make_float4(breg[0], breg[1], breg[2], breg[3]);                     \
        _d[1] = make_float4(breg[4], breg[5], breg[6], breg[7]);                     \
    } while (0)

    #define COMPUTE_KS(ks) do {                                                      \
        const int kc = (ks)*8 + tg;                                                  \
        uint32_t afr[4][4];                                                          \
        _Pragma("unroll")                                                            \
        for (int mi = 0; mi < 4; mi++) {                                             \
            const uint32_t* p = Aw + mi*16*PADK + kc;                                \
            afr[mi][0] = p[0];                                                       \
            afr[mi][1] = p[8*PADK];                                                  \
            afr[mi][2] = p[4];                                                       \
            afr[mi][3] = p[8*PADK + 4];                                              \
        }                                                                            \
        _Pragma("unroll")                                                            \
        for (int ni = 0; ni < 8; ni++) {                                             \
            const uint32_t* q = Bw + ni*8*PADK + kc;                                 \
            uint32_t b0 = q[0], b1 = q[4];                                           \
            _Pragma("unroll")                                                        \
            for (int mi = 0; mi < 4; mi++)                                           \
                mma_tf32(acc[mi][ni], afr[mi], b0, b1);                              \
        }                                                                            \
    } while (0)

    float acc[4][8][4];
    #pragma unroll
    for (int mi = 0; mi < 4; mi++)
        #pragma unroll
        for (int ni = 0; ni < 8; ni++)
            #pragma unroll
            for (int qq = 0; qq < 4; qq++) acc[mi][ni][qq] = 0.f;

    // ---- prologue: stage A(0), B(0) ----
    ISSUE_A(0, 0);
    #pragma unroll
    for (int q = 0; q < 4; q++) { LDG_Q(0, q); STS_Q(0, q); }
    CP_WAIT0();
    __syncthreads();

    int sB = 0, sBn = 1;
    for (int kt = 0; kt < NKT; kt++) {
        const int sA = kt & 1;
        const bool more = (kt + 1 < NKT);
        if (more) ISSUE_A(kt + 1, sA ^ 1);

        const uint32_t* Aw = (const uint32_t*)(As + sA*ASTG + (wm*64 + g)*PADK);
        const uint32_t* Bw = (const uint32_t*)(Bs + sB*BSTG + (wn*64 + g)*PADK);

        if (more) LDG_Q(kt + 1, 0);
        COMPUTE_KS(0);
        if (more) { STS_Q(sBn, 0); LDG_Q(kt + 1, 1); }
        COMPUTE_KS(1);
        if (more) { STS_Q(sBn, 1); LDG_Q(kt + 1, 2); }
        COMPUTE_KS(2);
        if (more) { STS_Q(sBn, 2); LDG_Q(kt + 1, 3); }
        COMPUTE_KS(3);
        if (more) {
            STS_Q(sBn, 3);
            CP_WAIT0();
            __syncthreads();
        }
        sB = sBn;
        sBn = (sBn == 2) ? 0 : sBn + 1;
    }

    // ---- epilogue ----
    float* ob = out + (size_t)b * O_ * NPIX;
    #pragma unroll
    for (int mi = 0; mi < 4; mi++) {
        const int r0 = tile_m*128 + wm*64 + mi*16 + g;
        #pragma unroll
        for (int ni = 0; ni < 8; ni++) {
            const int cb = nBase + wn*64 + ni*8 + 2*tg;
            if (cb < NPIX) {
                *(float2*)(ob + (size_t)r0*NPIX + cb)     = make_float2(acc[mi][ni][0], acc[mi][ni][1]);
                *(float2*)(ob + (size_t)(r0+8)*NPIX + cb) = make_float2(acc[mi][ni][2], acc[mi][ni][3]);
            }
        }
    }
    #undef ISSUE_A
    #undef LDG_Q
    #undef STS_Q
    #undef COMPUTE_KS
}

// ===========================================================================
extern "C" void kernel_launch(void* const* d_in, const int* in_sizes, int n_in,
                              void* d_out, int out_size) {
    const float* x       = (const float*)d_in[0];
    const float* experts = (const float*)d_in[1];
    const float* rw1     = (const float*)d_in[2];
    const float* rb1     = (const float*)d_in[3];
    const float* rw2     = (const float*)d_in[4];
    const float* rb2     = (const float*)d_in[5];
    float* out           = (float*)d_out;

    static bool attr_set = false;
    if (!attr_set) {
        cudaFuncSetAttribute(conv_mma_kernel,
                             cudaFuncAttributeMaxDynamicSharedMemorySize, CONV_SMEM);
        attr_set = true;
    }

    pad_pool_kernel<<<dim3(C_, B_), 128>>>(x);
    mlp_kernel<<<B_, 64>>>(rw1, rb1, rw2, rb2);
    combine_kernel<<<dim3(576, B_), 256>>>(experts);
    conv_mma_kernel<<<dim3(NTILES, 2, B_), 384, CONV_SMEM>>>(out);
}

// round 13
// speedup vs baseline: 1.5680x; 1.5680x over previous
#include <cuda_runtime.h>
#include <cuda_bf16.h>
#include <stdint.h>
#include <math.h>

#define B_   32
#define C_   256
#define HH   56
#define WW   56
#define E_   4
#define O_   256
#define HID_ 64
#define NPIX 3136
#define KDIM 2304
#define WPERB (O_*KDIM)
#define BK   32
#define NKT  (KDIM/BK)                // 72 k-tiles
#define PIMG 3364                     // 58*58 padded plane
#define STG  4352                     // floats per stage block: 32 k x 136
#define KROW 136                      // padded row stride (floats)

// ---------------- device scratch (no runtime allocation) ----------------
__device__ float g_routing[B_*E_];
__device__ float g_pooled[B_*C_];
__device__ int   g_ktab[KDIM];
// A tf32, k-major packed blocks: [b][tile_m(2)][kt(72)] -> [k(32)][m(136 pad)]
__device__ __align__(16) float g_combined[(size_t)B_*2*NKT*STG];
__device__ __align__(16) float g_xpad[(size_t)B_*C_*PIMG + 4096]; // padded tf32 x

// ---------------- helpers ----------------
__device__ __forceinline__ uint32_t f2tf32(float f) {
    uint32_t u;
    asm("cvt.rna.tf32.f32 %0, %1;" : "=r"(u) : "f"(f));
    return u;
}

__device__ __forceinline__ void mma_tf32(float* d, const uint32_t* a, uint32_t b0, uint32_t b1) {
    asm volatile(
        "mma.sync.aligned.m16n8k8.row.col.f32.tf32.tf32.f32 "
        "{%0,%1,%2,%3}, {%4,%5,%6,%7}, {%8,%9}, {%0,%1,%2,%3};"
        : "+f"(d[0]), "+f"(d[1]), "+f"(d[2]), "+f"(d[3])
        : "r"(a[0]), "r"(a[1]), "r"(a[2]), "r"(a[3]), "r"(b0), "r"(b1));
}

#define CP_ASYNC16(dst_u32, src_ptr) \
    asm volatile("cp.async.cg.shared.global [%0], [%1], 16;" :: "r"(dst_u32), "l"(src_ptr))
#define CP_ASYNC4(dst_u32, src_ptr) \
    asm volatile("cp.async.ca.shared.global [%0], [%1], 4;" :: "r"(dst_u32), "l"(src_ptr))
#define CP_COMMIT() asm volatile("cp.async.commit_group;" ::: "memory")
#define CP_WAIT0()  asm volatile("cp.async.wait_group 0;"  ::: "memory")
#define CP_WAIT1()  asm volatile("cp.async.wait_group 1;"  ::: "memory")

// ===========================================================================
// Kernel 1a: fused zero-pad + tf32-round + global average pool.
// ===========================================================================
__global__ void __launch_bounds__(128) pad_pool_kernel(const float* __restrict__ x) {
    const int c = blockIdx.x, b = blockIdx.y;
    const int tid = threadIdx.x;
    const float* src = x + ((size_t)b*C_ + c)*NPIX;
    float* dst = g_xpad + ((size_t)b*C_ + c)*PIMG;

    float s = 0.f;
    for (int idx = tid; idx < PIMG; idx += 128) {
        const int py = idx / 58;
        const int px = idx - py*58;
        float v = 0.f;
        if ((unsigned)(py-1) < 56u && (unsigned)(px-1) < 56u) {
            v = src[(py-1)*WW + (px-1)];
            s += v;
        }
        dst[idx] = __uint_as_float(f2tf32(v));
    }
    #pragma unroll
    for (int o = 16; o; o >>= 1) s += __shfl_xor_sync(0xffffffffu, s, o);
    __shared__ float ws[4];
    if ((tid & 31) == 0) ws[tid >> 5] = s;
    __syncthreads();
    if (tid == 0) g_pooled[b*C_ + c] = (ws[0]+ws[1]+ws[2]+ws[3]) * (1.0f/(float)NPIX);
}

// ===========================================================================
// Kernel 1b: MLP + softmax routing. grid B_, 64 threads. Block 0 also fills ktab.
// ===========================================================================
__global__ void __launch_bounds__(64) mlp_kernel(const float* __restrict__ rw1,
                                                 const float* __restrict__ rb1,
                                                 const float* __restrict__ rw2,
                                                 const float* __restrict__ rb2) {
    const int b = blockIdx.x, t = threadIdx.x;
    if (b == 0) {
        for (int k = t; k < KDIM; k += 64) {
            int c = k / 9, rem = k - 9*c;
            int ky = rem / 3 - 1, kx = rem % 3 - 1;
            g_ktab[k] = c*PIMG + ky*58 + kx;
        }
    }
    __shared__ float pl[C_];
    __shared__ float hid[HID_];
    __shared__ float logits[E_];
    for (int c = t; c < C_; c += 64) pl[c] = g_pooled[b*C_ + c];
    __syncthreads();
    {
        float s = rb1[t];
        const float* w = rw1 + t * C_;
        #pragma unroll 8
        for (int c = 0; c < C_; c++) s = fmaf(w[c], pl[c], s);
        hid[t] = fmaxf(s, 0.f);
    }
    __syncthreads();
    if (t < E_) {
        float s = rb2[t];
        const float* w = rw2 + t * HID_;
        #pragma unroll 8
        for (int h = 0; h < HID_; h++) s = fmaf(w[h], hid[h], s);
        logits[t] = s;
    }
    __syncthreads();
    if (t == 0) {
        float m = logits[0];
        #pragma unroll
        for (int e = 1; e < E_; e++) m = fmaxf(m, logits[e]);
        float ex[E_], sum = 0.f;
        #pragma unroll
        for (int e = 0; e < E_; e++) { ex[e] = expf(logits[e] - m); sum += ex[e]; }
        float inv = 1.0f / sum;
        #pragma unroll
        for (int e = 0; e < E_; e++) g_routing[b*E_ + e] = ex[e] * inv;
    }
}

// ===========================================================================
// Kernel 2: mix experts -> k-major packed tf32 A blocks [32][136].
//   grid (2*NKT, B_), 256 threads, smem-staged transpose.
// ===========================================================================
__global__ void __launch_bounds__(256) combine_kernel(const float* __restrict__ experts) {
    __shared__ float st[128*33];
    const int b  = blockIdx.y;
    const int bx = blockIdx.x;                 // tile_m*NKT + kt
    const int tile_m = bx / NKT;
    const int kt = bx - tile_m*NKT;
    const int tid = threadIdx.x;

    const float r0 = g_routing[b*E_+0], r1 = g_routing[b*E_+1];
    const float r2 = g_routing[b*E_+2], r3 = g_routing[b*E_+3];

    // read 128 rows x 32 k (mixed, tf32-rounded) into smem [m][33]
    const int row = tid >> 1, seg = tid & 1;
    const size_t base = (size_t)(tile_m*128 + row)*KDIM + kt*32 + seg*16;
    #pragma unroll
    for (int q = 0; q < 4; q++) {
        float4 a = *(const float4*)(experts + base + 4*q);
        float4 c = *(const float4*)(experts + (size_t)WPERB   + base + 4*q);
        float4 d = *(const float4*)(experts + (size_t)2*WPERB + base + 4*q);
        float4 f = *(const float4*)(experts + (size_t)3*WPERB + base + 4*q);
        float* dst = st + row*33 + seg*16 + 4*q;
        dst[0] = __uint_as_float(f2tf32(r0*a.x + r1*c.x + r2*d.x + r3*f.x));
        dst[1] = __uint_as_float(f2tf32(r0*a.y + r1*c.y + r2*d.y + r3*f.y));
        dst[2] = __uint_as_float(f2tf32(r0*a.z + r1*c.z + r2*d.z + r3*f.z));
        dst[3] = __uint_as_float(f2tf32(r0*a.w + r1*c.w + r2*d.w + r3*f.w));
    }
    __syncthreads();

    // transpose out: [k][136]; thread: k = tid>>3, m0 = (tid&7)*16
    float* outp = g_combined + ((size_t)(b*2 + tile_m)*NKT + kt)*STG;
    const int k  = tid >> 3;
    const int m0 = (tid & 7) * 16;
    #pragma unroll
    for (int i = 0; i < 4; i++) {
        const float* s = st + (m0 + 4*i)*33 + k;
        float4 v = make_float4(s[0], s[33], s[66], s[99]);
        *(float4*)(outp + k*KROW + m0 + 4*i) = v;
    }
}

// ===========================================================================
// Kernel 3: TF32 mma.sync implicit-GEMM conv, fully-async 3-stage pipeline.
//   CTA 128(oc) x 128(px), 8 warps = 2(m) x 4(n), warp tile 64x32, 2 CTAs/SM.
//   A: linear cp.async of packed [32][136] blocks.
//   B: cp.async.ca 4B im2col gather from pre-padded tf32 g_xpad.
//   smem: A stages [0, 3*STG), B stages [3*STG, 6*STG). 102 KB.
// ===========================================================================
__global__ void __launch_bounds__(256, 2) conv_mma_kernel(float* __restrict__ out) {
    extern __shared__ float sm[];
    float* As = sm;
    float* Bs = sm + 3*STG;

    const int tid    = threadIdx.x;
    const int lane   = tid & 31;
    const int warp   = tid >> 5;
    const int nBase  = blockIdx.x * 128;
    const int tile_m = blockIdx.y;
    const int b      = blockIdx.z;

    const int g  = lane >> 2;      // 0..7
    const int tg = lane & 3;       // 0..3
    const int wm = warp >> 2;      // 0..1 (m)
    const int wn = warp & 3;       // 0..3 (n)

    const float* Ab = g_combined + ((size_t)(b*2 + tile_m)*NKT)*STG;

    // B producer: pixel nl, k-half kh
    const int nl = tid & 127;
    const int kh = tid >> 7;
    const int n  = nBase + nl;
    const int ny = n / WW, nx = n - (n / WW) * WW;
    const float* xpb = g_xpad + (size_t)b*C_*PIMG + (ny+1)*58 + (nx+1);

    const uint32_t sb  = (uint32_t)__cvta_generic_to_shared(sm);
    const uint32_t sbB = sb + 3*STG*4u;

    // issue one tile's A (linear 17 KB) + B (16 cp.async 4B gather); 1 group
    #define ISSUE(kt_, s) do {                                                       \
        const float* _as = Ab + (size_t)(kt_)*STG;                                   \
        _Pragma("unroll")                                                            \
        for (int i = 0; i < 5; i++) {                                                \
            int idx = tid + i*256;                                                   \
            if (idx < 1088)                                                          \
                CP_ASYNC16(sb + (uint32_t)((s)*STG + idx*4)*4u, _as + idx*4);        \
        }                                                                            \
        {                                                                            \
            const int4* _t4 = (const int4*)(g_ktab + (kt_)*BK + kh*16);              \
            const uint32_t _d0 = sbB + (uint32_t)((s)*STG + kh*16*KROW + nl)*4u;     \
            _Pragma("unroll")                                                        \
            for (int qq = 0; qq < 4; qq++) {                                         \
                int4 kv = _t4[qq];                                                   \
                CP_ASYNC4(_d0 + (qq*4+0)*KROW*4u, xpb + kv.x);                       \
                CP_ASYNC4(_d0 + (qq*4+1)*KROW*4u, xpb + kv.y);                       \
                CP_ASYNC4(_d0 + (qq*4+2)*KROW*4u, xpb + kv.z);                       \
                CP_ASYNC4(_d0 + (qq*4+3)*KROW*4u, xpb + kv.w);                       \
            }                                                                        \
        }                                                                            \
        CP_COMMIT();                                                                 \
    } while (0)

    #define COMPUTE_KS(ks) do {                                                      \
        uint32_t afr[4][4];                                                          \
        _Pragma("unroll")                                                            \
        for (int mi = 0; mi < 4; mi++) {                                             \
            const uint32_t* p = Aw + (ks)*(8*KROW) + mi*16;                          \
            afr[mi][0] = p[0];                                                       \
            afr[mi][1] = p[8];                                                       \
            afr[mi][2] = p[4*KROW];                                                  \
            afr[mi][3] = p[4*KROW + 8];                                              \
        }                                                                            \
        _Pragma("unroll")                                                            \
        for (int ni = 0; ni < 4; ni++) {                                             \
            const uint32_t* q = Bw + (ks)*(8*KROW) + ni*8;                           \
            uint32_t b0 = q[0], b1 = q[4*KROW];                                      \
            _Pragma("unroll")                                                        \
            for (int mi = 0; mi < 4; mi++)                                           \
                mma_tf32(acc[mi][ni], afr[mi], b0, b1);                              \
        }                                                                            \
    } while (0)

    float acc[4][4][4];
    #pragma unroll
    for (int mi = 0; mi < 4; mi++)
        #pragma unroll
        for (int ni = 0; ni < 4; ni++)
            #pragma unroll
            for (int qq = 0; qq < 4; qq++) acc[mi][ni][qq] = 0.f;

    // ---- prologue: tiles 0,1 in flight ----
    ISSUE(0, 0);
    ISSUE(1, 1);
    CP_WAIT1();
    __syncthreads();

    int sCur = 0;
    for (int kt = 0; kt < NKT; kt++) {
        const int sNxt2 = (sCur == 0) ? 2 : sCur - 1;   // (kt+2)%3 == (kt-1)%3
        if (kt + 2 < NKT) ISSUE(kt + 2, sNxt2);

        const uint32_t* Aw = (const uint32_t*)(As + sCur*STG + tg*KROW + wm*64 + g);
        const uint32_t* Bw = (const uint32_t*)(Bs + sCur*STG + tg*KROW + wn*32 + g);

        COMPUTE_KS(0);
        COMPUTE_KS(1);
        COMPUTE_KS(2);
        COMPUTE_KS(3);

        if (kt + 1 < NKT) {
            if (kt + 2 < NKT) { CP_WAIT1(); }
            else              { CP_WAIT0(); }
            __syncthreads();
        }
        sCur = (sCur == 2) ? 0 : sCur + 1;
    }

    // ---- epilogue ----
    float* ob = out + (size_t)b * O_ * NPIX;
    #pragma unroll
    for (int mi = 0; mi < 4; mi++) {
        const int r0 = tile_m*128 + wm*64 + mi*16 + g;
        #pragma unroll
        for (int ni = 0; ni < 4; ni++) {
            const int cb = nBase + wn*32 + ni*8 + 2*tg;
            if (cb < NPIX) {
                *(float2*)(ob + (size_t)r0*NPIX + cb)     = make_float2(acc[mi][ni][0], acc[mi][ni][1]);
                *(float2*)(ob + (size_t)(r0+8)*NPIX + cb) = make_float2(acc[mi][ni][2], acc[mi][ni][3]);
            }
        }
    }
    #undef ISSUE
    #undef COMPUTE_KS
}

#define CONV_SMEM (6*STG*4)   // 104448 B -> 2 CTAs/SM

// ===========================================================================
extern "C" void kernel_launch(void* const* d_in, const int* in_sizes, int n_in,
                              void* d_out, int out_size) {
    const float* x       = (const float*)d_in[0];
    const float* experts = (const float*)d_in[1];
    const float* rw1     = (const float*)d_in[2];
    const float* rb1     = (const float*)d_in[3];
    const float* rw2     = (const float*)d_in[4];
    const float* rb2     = (const float*)d_in[5];
    float* out           = (float*)d_out;

    static bool attr_set = false;
    if (!attr_set) {
        cudaFuncSetAttribute(conv_mma_kernel,
                             cudaFuncAttributeMaxDynamicSharedMemorySize, CONV_SMEM);
        attr_set = true;
    }

    pad_pool_kernel<<<dim3(C_, B_), 128>>>(x);
    mlp_kernel<<<B_, 64>>>(rw1, rb1, rw2, rb2);
    combine_kernel<<<dim3(2*NKT, B_), 256>>>(experts);
    conv_mma_kernel<<<dim3(25, 2, B_), 256, CONV_SMEM>>>(out);
}

// round 14
// speedup vs baseline: 1.6206x; 1.0335x over previous
#include <cuda_runtime.h>
#include <cuda_bf16.h>
#include <stdint.h>
#include <math.h>

#define B_   32
#define C_   256
#define HH   56
#define WW   56
#define E_   4
#define O_   256
#define HID_ 64
#define NPIX 3136
#define KDIM 2304
#define WPERB (O_*KDIM)
#define BK   32
#define NKT  (KDIM/BK)                // 72 k-tiles
#define PIMG 3364                     // 58*58 padded plane
#define STG  4352                     // floats per stage block: 32 k x 136
#define KROW 136                      // padded row stride (floats)

// ---------------- device scratch (no runtime allocation) ----------------
__device__ float g_routing[B_*E_];
__device__ float g_pooled[B_*C_];
__device__ int   g_ktab[KDIM];
// A tf32, k-major packed blocks: [b][tile_m(2)][kt(72)] -> [k(32)][m(136 pad)]
__device__ __align__(16) float g_combined[(size_t)B_*2*NKT*STG];
__device__ __align__(16) float g_xpad[(size_t)B_*C_*PIMG + 4096]; // padded tf32 x

// ---------------- helpers ----------------
__device__ __forceinline__ uint32_t f2tf32(float f) {
    uint32_t u;
    asm("cvt.rna.tf32.f32 %0, %1;" : "=r"(u) : "f"(f));
    return u;
}

__device__ __forceinline__ void mma_tf32(float* d, const uint32_t* a, uint32_t b0, uint32_t b1) {
    asm volatile(
        "mma.sync.aligned.m16n8k8.row.col.f32.tf32.tf32.f32 "
        "{%0,%1,%2,%3}, {%4,%5,%6,%7}, {%8,%9}, {%0,%1,%2,%3};"
        : "+f"(d[0]), "+f"(d[1]), "+f"(d[2]), "+f"(d[3])
        : "r"(a[0]), "r"(a[1]), "r"(a[2]), "r"(a[3]), "r"(b0), "r"(b1));
}

#define CP_ASYNC16(dst_u32, src_ptr) \
    asm volatile("cp.async.cg.shared.global [%0], [%1], 16;" :: "r"(dst_u32), "l"(src_ptr))
#define CP_ASYNC4(dst_u32, src_ptr) \
    asm volatile("cp.async.ca.shared.global [%0], [%1], 4;" :: "r"(dst_u32), "l"(src_ptr))
#define CP_COMMIT() asm volatile("cp.async.commit_group;" ::: "memory")
#define CP_WAIT0()  asm volatile("cp.async.wait_group 0;"  ::: "memory")
#define CP_WAIT1()  asm volatile("cp.async.wait_group 1;"  ::: "memory")

// ===========================================================================
// Kernel 1a: fused zero-pad + tf32-round + global average pool.
// ===========================================================================
__global__ void __launch_bounds__(128) pad_pool_kernel(const float* __restrict__ x) {
    const int c = blockIdx.x, b = blockIdx.y;
    const int tid = threadIdx.x;
    const float* src = x + ((size_t)b*C_ + c)*NPIX;
    float* dst = g_xpad + ((size_t)b*C_ + c)*PIMG;

    float s = 0.f;
    for (int idx = tid; idx < PIMG; idx += 128) {
        const int py = idx / 58;
        const int px = idx - py*58;
        float v = 0.f;
        if ((unsigned)(py-1) < 56u && (unsigned)(px-1) < 56u) {
            v = src[(py-1)*WW + (px-1)];
            s += v;
        }
        dst[idx] = __uint_as_float(f2tf32(v));
    }
    #pragma unroll
    for (int o = 16; o; o >>= 1) s += __shfl_xor_sync(0xffffffffu, s, o);
    __shared__ float ws[4];
    if ((tid & 31) == 0) ws[tid >> 5] = s;
    __syncthreads();
    if (tid == 0) g_pooled[b*C_ + c] = (ws[0]+ws[1]+ws[2]+ws[3]) * (1.0f/(float)NPIX);
}

// ===========================================================================
// Kernel 1b: MLP + softmax routing. grid B_, 64 threads. Block 0 also fills ktab.
// ===========================================================================
__global__ void __launch_bounds__(64) mlp_kernel(const float* __restrict__ rw1,
                                                 const float* __restrict__ rb1,
                                                 const float* __restrict__ rw2,
                                                 const float* __restrict__ rb2) {
    const int b = blockIdx.x, t = threadIdx.x;
    if (b == 0) {
        for (int k = t; k < KDIM; k += 64) {
            int c = k / 9, rem = k - 9*c;
            int ky = rem / 3 - 1, kx = rem % 3 - 1;
            g_ktab[k] = c*PIMG + ky*58 + kx;
        }
    }
    __shared__ float pl[C_];
    __shared__ float hid[HID_];
    __shared__ float logits[E_];
    for (int c = t; c < C_; c += 64) pl[c] = g_pooled[b*C_ + c];
    __syncthreads();
    {
        float s = rb1[t];
        const float* w = rw1 + t * C_;
        #pragma unroll 8
        for (int c = 0; c < C_; c++) s = fmaf(w[c], pl[c], s);
        hid[t] = fmaxf(s, 0.f);
    }
    __syncthreads();
    if (t < E_) {
        float s = rb2[t];
        const float* w = rw2 + t * HID_;
        #pragma unroll 8
        for (int h = 0; h < HID_; h++) s = fmaf(w[h], hid[h], s);
        logits[t] = s;
    }
    __syncthreads();
    if (t == 0) {
        float m = logits[0];
        #pragma unroll
        for (int e = 1; e < E_; e++) m = fmaxf(m, logits[e]);
        float ex[E_], sum = 0.f;
        #pragma unroll
        for (int e = 0; e < E_; e++) { ex[e] = expf(logits[e] - m); sum += ex[e]; }
        float inv = 1.0f / sum;
        #pragma unroll
        for (int e = 0; e < E_; e++) g_routing[b*E_ + e] = ex[e] * inv;
    }
}

// ===========================================================================
// Kernel 2: mix experts -> k-major packed tf32 A blocks [32][136].
//   grid (2*NKT, B_), 256 threads, smem-staged transpose.
//   Read phase: row-major float4 sweep (coalesced). Write phase: coalesced.
// ===========================================================================
__global__ void __launch_bounds__(256) combine_kernel(const float* __restrict__ experts) {
    __shared__ float st[128*33];
    const int b  = blockIdx.y;
    const int bx = blockIdx.x;                 // tile_m*NKT + kt
    const int tile_m = bx / NKT;
    const int kt = bx - tile_m*NKT;
    const int tid = threadIdx.x;

    const float r0 = g_routing[b*E_+0], r1 = g_routing[b*E_+1];
    const float r2 = g_routing[b*E_+2], r3 = g_routing[b*E_+3];

    // read 128 rows x 32 k: 1024 float4, coalesced (8 float4 per row)
    #pragma unroll
    for (int i = 0; i < 4; i++) {
        const int idx = tid + i*256;
        const int row = idx >> 3, c4 = idx & 7;
        const size_t base = (size_t)(tile_m*128 + row)*KDIM + kt*32 + c4*4;
        float4 a = *(const float4*)(experts + base);
        float4 c = *(const float4*)(experts + (size_t)WPERB   + base);
        float4 d = *(const float4*)(experts + (size_t)2*WPERB + base);
        float4 f = *(const float4*)(experts + (size_t)3*WPERB + base);
        float* dst = st + row*33 + c4*4;
        dst[0] = __uint_as_float(f2tf32(r0*a.x + r1*c.x + r2*d.x + r3*f.x));
        dst[1] = __uint_as_float(f2tf32(r0*a.y + r1*c.y + r2*d.y + r3*f.y));
        dst[2] = __uint_as_float(f2tf32(r0*a.z + r1*c.z + r2*d.z + r3*f.z));
        dst[3] = __uint_as_float(f2tf32(r0*a.w + r1*c.w + r2*d.w + r3*f.w));
    }
    __syncthreads();

    // transpose out: [k][136]; thread: k = tid>>3, m0 = (tid&7)*16 (coalesced writes)
    float* outp = g_combined + ((size_t)(b*2 + tile_m)*NKT + kt)*STG;
    const int k  = tid >> 3;
    const int m0 = (tid & 7) * 16;
    #pragma unroll
    for (int i = 0; i < 4; i++) {
        const float* s = st + (m0 + 4*i)*33 + k;
        float4 v = make_float4(s[0], s[33], s[66], s[99]);
        *(float4*)(outp + k*KROW + m0 + 4*i) = v;
    }
}

// ===========================================================================
// Kernel 3: TF32 mma.sync implicit-GEMM conv, fully-async 3-stage pipeline,
//   A-fragment double buffering across ks (overlap LDS with MMA).
//   CTA 128(oc) x 128(px), 8 warps = 2(m) x 4(n), warp tile 64x32, 2 CTAs/SM.
// ===========================================================================
__global__ void __launch_bounds__(256, 2) conv_mma_kernel(float* __restrict__ out) {
    extern __shared__ float sm[];
    float* As = sm;
    float* Bs = sm + 3*STG;

    const int tid    = threadIdx.x;
    const int lane   = tid & 31;
    const int warp   = tid >> 5;
    const int nBase  = blockIdx.x * 128;
    const int tile_m = blockIdx.y;
    const int b      = blockIdx.z;

    const int g  = lane >> 2;      // 0..7
    const int tg = lane & 3;       // 0..3
    const int wm = warp >> 2;      // 0..1 (m)
    const int wn = warp & 3;       // 0..3 (n)

    const float* Ab = g_combined + ((size_t)(b*2 + tile_m)*NKT)*STG;

    // B producer: pixel nl, k-half kh
    const int nl = tid & 127;
    const int kh = tid >> 7;
    const int n  = nBase + nl;
    const int ny = n / WW, nx = n - (n / WW) * WW;
    const float* xpb = g_xpad + (size_t)b*C_*PIMG + (ny+1)*58 + (nx+1);

    const uint32_t sb  = (uint32_t)__cvta_generic_to_shared(sm);
    const uint32_t sbB = sb + 3*STG*4u;

    // issue one tile's A (linear 17 KB) + B (16 cp.async 4B gather); 1 group
    #define ISSUE(kt_, s) do {                                                       \
        const float* _as = Ab + (size_t)(kt_)*STG;                                   \
        _Pragma("unroll")                                                            \
        for (int i = 0; i < 5; i++) {                                                \
            int idx = tid + i*256;                                                   \
            if (idx < 1088)                                                          \
                CP_ASYNC16(sb + (uint32_t)((s)*STG + idx*4)*4u, _as + idx*4);        \
        }                                                                            \
        {                                                                            \
            const int4* _t4 = (const int4*)(g_ktab + (kt_)*BK + kh*16);              \
            const uint32_t _d0 = sbB + (uint32_t)((s)*STG + kh*16*KROW + nl)*4u;     \
            _Pragma("unroll")                                                        \
            for (int qq = 0; qq < 4; qq++) {                                         \
                int4 kv = _t4[qq];                                                   \
                CP_ASYNC4(_d0 + (qq*4+0)*KROW*4u, xpb + kv.x);                       \
                CP_ASYNC4(_d0 + (qq*4+1)*KROW*4u, xpb + kv.y);                       \
                CP_ASYNC4(_d0 + (qq*4+2)*KROW*4u, xpb + kv.z);                       \
                CP_ASYNC4(_d0 + (qq*4+3)*KROW*4u, xpb + kv.w);                       \
            }                                                                        \
        }                                                                            \
        CP_COMMIT();                                                                 \
    } while (0)

    #define LOAD_AFR(dst, ks) do {                                                   \
        _Pragma("unroll")                                                            \
        for (int mi = 0; mi < 4; mi++) {                                             \
            const uint32_t* p = Aw + (ks)*(8*KROW) + mi*16;                          \
            (dst)[mi][0] = p[0];                                                     \
            (dst)[mi][1] = p[8];                                                     \
            (dst)[mi][2] = p[4*KROW];                                                \
            (dst)[mi][3] = p[4*KROW + 8];                                            \
        }                                                                            \
    } while (0)

    #define MMA_KS(afr_, ks) do {                                                    \
        _Pragma("unroll")                                                            \
        for (int ni = 0; ni < 4; ni++) {                                             \
            const uint32_t* q = Bw + (ks)*(8*KROW) + ni*8;                           \
            uint32_t b0 = q[0], b1 = q[4*KROW];                                      \
            _Pragma("unroll")                                                        \
            for (int mi = 0; mi < 4; mi++)                                           \
                mma_tf32(acc[mi][ni], (afr_)[mi], b0, b1);                           \
        }                                                                            \
    } while (0)

    float acc[4][4][4];
    #pragma unroll
    for (int mi = 0; mi < 4; mi++)
        #pragma unroll
        for (int ni = 0; ni < 4; ni++)
            #pragma unroll
            for (int qq = 0; qq < 4; qq++) acc[mi][ni][qq] = 0.f;

    // ---- prologue: tiles 0,1 in flight ----
    ISSUE(0, 0);
    ISSUE(1, 1);
    CP_WAIT1();
    __syncthreads();

    int sCur = 0;
    for (int kt = 0; kt < NKT; kt++) {
        const int sNxt2 = (sCur == 0) ? 2 : sCur - 1;   // (kt+2)%3
        if (kt + 2 < NKT) ISSUE(kt + 2, sNxt2);

        const uint32_t* Aw = (const uint32_t*)(As + sCur*STG + tg*KROW + wm*64 + g);
        const uint32_t* Bw = (const uint32_t*)(Bs + sCur*STG + tg*KROW + wn*32 + g);

        // software-pipelined ks loop: load ks+1 A-frags during ks MMAs
        uint32_t afr[2][4][4];
        LOAD_AFR(afr[0], 0);
        LOAD_AFR(afr[1], 1);
        MMA_KS(afr[0], 0);
        LOAD_AFR(afr[0], 2);
        MMA_KS(afr[1], 1);
        LOAD_AFR(afr[1], 3);
        MMA_KS(afr[0], 2);
        MMA_KS(afr[1], 3);

        if (kt + 1 < NKT) {
            if (kt + 2 < NKT) { CP_WAIT1(); }
            else              { CP_WAIT0(); }
            __syncthreads();
        }
        sCur = (sCur == 2) ? 0 : sCur + 1;
    }

    // ---- epilogue ----
    float* ob = out + (size_t)b * O_ * NPIX;
    #pragma unroll
    for (int mi = 0; mi < 4; mi++) {
        const int r0 = tile_m*128 + wm*64 + mi*16 + g;
        #pragma unroll
        for (int ni = 0; ni < 4; ni++) {
            const int cb = nBase + wn*32 + ni*8 + 2*tg;
            if (cb < NPIX) {
                *(float2*)(ob + (size_t)r0*NPIX + cb)     = make_float2(acc[mi][ni][0], acc[mi][ni][1]);
                *(float2*)(ob + (size_t)(r0+8)*NPIX + cb) = make_float2(acc[mi][ni][2], acc[mi][ni][3]);
            }
        }
    }
    #undef ISSUE
    #undef LOAD_AFR
    #undef MMA_KS
}

#define CONV_SMEM (6*STG*4)   // 104448 B -> 2 CTAs/SM

// ===========================================================================
extern "C" void kernel_launch(void* const* d_in, const int* in_sizes, int n_in,
                              void* d_out, int out_size) {
    const float* x       = (const float*)d_in[0];
    const float* experts = (const float*)d_in[1];
    const float* rw1     = (const float*)d_in[2];
    const float* rb1     = (const float*)d_in[3];
    const float* rw2     = (const float*)d_in[4];
    const float* rb2     = (const float*)d_in[5];
    float* out           = (float*)d_out;

    static bool attr_set = false;
    if (!attr_set) {
        cudaFuncSetAttribute(conv_mma_kernel,
                             cudaFuncAttributeMaxDynamicSharedMemorySize, CONV_SMEM);
        attr_set = true;
    }

    pad_pool_kernel<<<dim3(C_, B_), 128>>>(x);
    mlp_kernel<<<B_, 64>>>(rw1, rb1, rw2, rb2);
    combine_kernel<<<dim3(2*NKT, B_), 256>>>(experts);
    conv_mma_kernel<<<dim3(25, 2, B_), 256, CONV_SMEM>>>(out);
}

// round 15
// speedup vs baseline: 1.6459x; 1.0156x over previous
#include <cuda_runtime.h>
#include <cuda_bf16.h>
#include <stdint.h>
#include <math.h>

#define B_   32
#define C_   256
#define HH   56
#define WW   56
#define E_   4
#define O_   256
#define HID_ 64
#define NPIX 3136
#define KDIM 2304
#define WPERB (O_*KDIM)
#define BK   48
#define NKT  (KDIM/BK)                // 48 k-tiles
#define PIMG 3364                     // 58*58 padded plane
#define KROW 136                      // padded m stride (floats)
#define STG  (BK*KROW)                // 6528 floats per stage block

// ---------------- device scratch (no runtime allocation) ----------------
__device__ float g_routing[B_*E_];
__device__ float g_pooled[B_*C_];
__device__ int   g_ktab[KDIM];
// A tf32, k-major packed blocks: [b][tile_m(2)][kt(48)] -> [k(48)][m(136 pad)]
__device__ __align__(16) float g_combined[(size_t)B_*2*NKT*STG];
__device__ __align__(16) float g_xpad[(size_t)B_*C_*PIMG + 4096]; // padded tf32 x

// ---------------- helpers ----------------
__device__ __forceinline__ uint32_t f2tf32(float f) {
    uint32_t u;
    asm("cvt.rna.tf32.f32 %0, %1;" : "=r"(u) : "f"(f));
    return u;
}

__device__ __forceinline__ void mma_tf32(float* d, const uint32_t* a, uint32_t b0, uint32_t b1) {
    asm volatile(
        "mma.sync.aligned.m16n8k8.row.col.f32.tf32.tf32.f32 "
        "{%0,%1,%2,%3}, {%4,%5,%6,%7}, {%8,%9}, {%0,%1,%2,%3};"
        : "+f"(d[0]), "+f"(d[1]), "+f"(d[2]), "+f"(d[3])
        : "r"(a[0]), "r"(a[1]), "r"(a[2]), "r"(a[3]), "r"(b0), "r"(b1));
}

#define CP_ASYNC16(dst_u32, src_ptr) \
    asm volatile("cp.async.cg.shared.global [%0], [%1], 16;" :: "r"(dst_u32), "l"(src_ptr))
#define CP_ASYNC4(dst_u32, src_ptr) \
    asm volatile("cp.async.ca.shared.global [%0], [%1], 4;" :: "r"(dst_u32), "l"(src_ptr))
#define CP_COMMIT() asm volatile("cp.async.commit_group;" ::: "memory")
#define CP_WAIT0()  asm volatile("cp.async.wait_group 0;"  ::: "memory")

// ===========================================================================
// Kernel 1a: fused zero-pad + tf32-round + global average pool.
// ===========================================================================
__global__ void __launch_bounds__(128) pad_pool_kernel(const float* __restrict__ x) {
    const int c = blockIdx.x, b = blockIdx.y;
    const int tid = threadIdx.x;
    const float* src = x + ((size_t)b*C_ + c)*NPIX;
    float* dst = g_xpad + ((size_t)b*C_ + c)*PIMG;

    float s = 0.f;
    for (int idx = tid; idx < PIMG; idx += 128) {
        const int py = idx / 58;
        const int px = idx - py*58;
        float v = 0.f;
        if ((unsigned)(py-1) < 56u && (unsigned)(px-1) < 56u) {
            v = src[(py-1)*WW + (px-1)];
            s += v;
        }
        dst[idx] = __uint_as_float(f2tf32(v));
    }
    #pragma unroll
    for (int o = 16; o; o >>= 1) s += __shfl_xor_sync(0xffffffffu, s, o);
    __shared__ float ws[4];
    if ((tid & 31) == 0) ws[tid >> 5] = s;
    __syncthreads();
    if (tid == 0) g_pooled[b*C_ + c] = (ws[0]+ws[1]+ws[2]+ws[3]) * (1.0f/(float)NPIX);
}

// ===========================================================================
// Kernel 1b: MLP + softmax routing. grid B_, 64 threads. Block 0 also fills ktab.
// ===========================================================================
__global__ void __launch_bounds__(64) mlp_kernel(const float* __restrict__ rw1,
                                                 const float* __restrict__ rb1,
                                                 const float* __restrict__ rw2,
                                                 const float* __restrict__ rb2) {
    const int b = blockIdx.x, t = threadIdx.x;
    if (b == 0) {
        for (int k = t; k < KDIM; k += 64) {
            int c = k / 9, rem = k - 9*c;
            int ky = rem / 3 - 1, kx = rem % 3 - 1;
            g_ktab[k] = c*PIMG + ky*58 + kx;
        }
    }
    __shared__ float pl[C_];
    __shared__ float hid[HID_];
    __shared__ float logits[E_];
    for (int c = t; c < C_; c += 64) pl[c] = g_pooled[b*C_ + c];
    __syncthreads();
    {
        float s = rb1[t];
        const float* w = rw1 + t * C_;
        #pragma unroll 8
        for (int c = 0; c < C_; c++) s = fmaf(w[c], pl[c], s);
        hid[t] = fmaxf(s, 0.f);
    }
    __syncthreads();
    if (t < E_) {
        float s = rb2[t];
        const float* w = rw2 + t * HID_;
        #pragma unroll 8
        for (int h = 0; h < HID_; h++) s = fmaf(w[h], hid[h], s);
        logits[t] = s;
    }
    __syncthreads();
    if (t == 0) {
        float m = logits[0];
        #pragma unroll
        for (int e = 1; e < E_; e++) m = fmaxf(m, logits[e]);
        float ex[E_], sum = 0.f;
        #pragma unroll
        for (int e = 0; e < E_; e++) { ex[e] = expf(logits[e] - m); sum += ex[e]; }
        float inv = 1.0f / sum;
        #pragma unroll
        for (int e = 0; e < E_; e++) g_routing[b*E_ + e] = ex[e] * inv;
    }
}

// ===========================================================================
// Kernel 2: mix experts -> k-major packed tf32 A blocks [48][136].
//   grid (2*NKT, B_), 256 threads, smem-staged transpose.
// ===========================================================================
__global__ void __launch_bounds__(256) combine_kernel(const float* __restrict__ experts) {
    __shared__ float st[128*49];
    const int b  = blockIdx.y;
    const int bx = blockIdx.x;                 // tile_m*NKT + kt
    const int tile_m = bx / NKT;
    const int kt = bx - tile_m*NKT;
    const int tid = threadIdx.x;

    const float r0 = g_routing[b*E_+0], r1 = g_routing[b*E_+1];
    const float r2 = g_routing[b*E_+2], r3 = g_routing[b*E_+3];

    // read 128 rows x 48 k: 1536 float4, coalesced (12 float4 per row)
    #pragma unroll
    for (int i = 0; i < 6; i++) {
        const int idx = tid + i*256;
        const int row = idx / 12, c4 = idx - row*12;
        const size_t base = (size_t)(tile_m*128 + row)*KDIM + kt*BK + c4*4;
        float4 a = *(const float4*)(experts + base);
        float4 c = *(const float4*)(experts + (size_t)WPERB   + base);
        float4 d = *(const float4*)(experts + (size_t)2*WPERB + base);
        float4 f = *(const float4*)(experts + (size_t)3*WPERB + base);
        float* dst = st + row*49 + c4*4;
        dst[0] = __uint_as_float(f2tf32(r0*a.x + r1*c.x + r2*d.x + r3*f.x));
        dst[1] = __uint_as_float(f2tf32(r0*a.y + r1*c.y + r2*d.y + r3*f.y));
        dst[2] = __uint_as_float(f2tf32(r0*a.z + r1*c.z + r2*d.z + r3*f.z));
        dst[3] = __uint_as_float(f2tf32(r0*a.w + r1*c.w + r2*d.w + r3*f.w));
    }
    __syncthreads();

    // transpose out: [k(48)][136]; tasks: 48 k x 8 m-chunks of 16
    float* outp = g_combined + ((size_t)(b*2 + tile_m)*NKT + kt)*STG;
    for (int t = tid; t < 384; t += 256) {
        const int k  = t >> 3;
        const int m0 = (t & 7) * 16;
        #pragma unroll
        for (int i = 0; i < 4; i++) {
            const float* s = st + (m0 + 4*i)*49 + k;
            float4 v = make_float4(s[0], s[49], s[98], s[147]);
            *(float4*)(outp + k*KROW + m0 + 4*i) = v;
        }
    }
}

// ===========================================================================
// Kernel 3: TF32 mma.sync implicit-GEMM conv, BK=48 (48 tiles, 6 ks each).
//   CTA 128(oc) x 128(px), 8 warps = 2(m) x 4(n), warp tile 64x32, 2 CTAs/SM.
//   A: linear cp.async of packed [48][136] blocks.
//   B: cp.async.ca 4B im2col gather from pre-padded tf32 g_xpad.
//   smem: A stages [0, 2*STG), B stages [2*STG, 4*STG). 104.4 KB.
// ===========================================================================
__global__ void __launch_bounds__(256, 2) conv_mma_kernel(float* __restrict__ out) {
    extern __shared__ float sm[];
    float* As = sm;
    float* Bs = sm + 2*STG;

    const int tid    = threadIdx.x;
    const int lane   = tid & 31;
    const int warp   = tid >> 5;
    const int nBase  = blockIdx.x * 128;
    const int tile_m = blockIdx.y;
    const int b      = blockIdx.z;

    const int g  = lane >> 2;      // 0..7
    const int tg = lane & 3;       // 0..3
    const int wm = warp >> 2;      // 0..1 (m)
    const int wn = warp & 3;       // 0..3 (n)

    const float* Ab = g_combined + ((size_t)(b*2 + tile_m)*NKT)*STG;

    // B producer: pixel nl, k-half kh (24 k each)
    const int nl = tid & 127;
    const int kh = tid >> 7;
    const int n  = nBase + nl;
    const int ny = n / WW, nx = n - (n / WW) * WW;
    const float* xpb = g_xpad + (size_t)b*C_*PIMG + (ny+1)*58 + (nx+1);

    const uint32_t sb  = (uint32_t)__cvta_generic_to_shared(sm);
    const uint32_t sbB = sb + 2*STG*4u;

    // issue one tile's A (linear 26 KB) + B (24 cp.async 4B gather); 1 group
    #define ISSUE(kt_, s) do {                                                       \
        const float* _as = Ab + (size_t)(kt_)*STG;                                   \
        _Pragma("unroll")                                                            \
        for (int i = 0; i < 7; i++) {                                                \
            int idx = tid + i*256;                                                   \
            if (idx < STG/4)                                                         \
                CP_ASYNC16(sb + (uint32_t)((s)*STG + idx*4)*4u, _as + idx*4);        \
        }                                                                            \
        {                                                                            \
            const int4* _t4 = (const int4*)(g_ktab + (kt_)*BK + kh*24);              \
            const uint32_t _d0 = sbB + (uint32_t)((s)*STG + kh*24*KROW + nl)*4u;     \
            _Pragma("unroll")                                                        \
            for (int qq = 0; qq < 6; qq++) {                                         \
                int4 kv = _t4[qq];                                                   \
                CP_ASYNC4(_d0 + (qq*4+0)*KROW*4u, xpb + kv.x);                       \
                CP_ASYNC4(_d0 + (qq*4+1)*KROW*4u, xpb + kv.y);                       \
                CP_ASYNC4(_d0 + (qq*4+2)*KROW*4u, xpb + kv.z);                       \
                CP_ASYNC4(_d0 + (qq*4+3)*KROW*4u, xpb + kv.w);                       \
            }                                                                        \
        }                                                                            \
        CP_COMMIT();                                                                 \
    } while (0)

    #define COMPUTE_KS(ks) do {                                                      \
        uint32_t afr[4][4];                                                          \
        _Pragma("unroll")                                                            \
        for (int mi = 0; mi < 4; mi++) {                                             \
            const uint32_t* p = Aw + (ks)*(8*KROW) + mi*16;                          \
            afr[mi][0] = p[0];                                                       \
            afr[mi][1] = p[8];                                                       \
            afr[mi][2] = p[4*KROW];                                                  \
            afr[mi][3] = p[4*KROW + 8];                                              \
        }                                                                            \
        _Pragma("unroll")                                                            \
        for (int ni = 0; ni < 4; ni++) {                                             \
            const uint32_t* q = Bw + (ks)*(8*KROW) + ni*8;                           \
            uint32_t b0 = q[0], b1 = q[4*KROW];                                      \
            _Pragma("unroll")                                                        \
            for (int mi = 0; mi < 4; mi++)                                           \
                mma_tf32(acc[mi][ni], afr[mi], b0, b1);                              \
        }                                                                            \
    } while (0)

    float acc[4][4][4];
    #pragma unroll
    for (int mi = 0; mi < 4; mi++)
        #pragma unroll
        for (int ni = 0; ni < 4; ni++)
            #pragma unroll
            for (int qq = 0; qq < 4; qq++) acc[mi][ni][qq] = 0.f;

    // ---- prologue ----
    ISSUE(0, 0);
    CP_WAIT0();
    __syncthreads();

    for (int kt = 0; kt < NKT; kt++) {
        const int cur = kt & 1;
        if (kt + 1 < NKT) ISSUE(kt + 1, cur ^ 1);

        const uint32_t* Aw = (const uint32_t*)(As + cur*STG + tg*KROW + wm*64 + g);
        const uint32_t* Bw = (const uint32_t*)(Bs + cur*STG + tg*KROW + wn*32 + g);

        COMPUTE_KS(0);
        COMPUTE_KS(1);
        COMPUTE_KS(2);
        COMPUTE_KS(3);
        COMPUTE_KS(4);
        COMPUTE_KS(5);

        if (kt + 1 < NKT) {
            CP_WAIT0();
            __syncthreads();
        }
    }

    // ---- epilogue ----
    float* ob = out + (size_t)b * O_ * NPIX;
    #pragma unroll
    for (int mi = 0; mi < 4; mi++) {
        const int r0 = tile_m*128 + wm*64 + mi*16 + g;
        #pragma unroll
        for (int ni = 0; ni < 4; ni++) {
            const int cb = nBase + wn*32 + ni*8 + 2*tg;
            if (cb < NPIX) {
                *(float2*)(ob + (size_t)r0*NPIX + cb)     = make_float2(acc[mi][ni][0], acc[mi][ni][1]);
                *(float2*)(ob + (size_t)(r0+8)*NPIX + cb) = make_float2(acc[mi][ni][2], acc[mi][ni][3]);
            }
        }
    }
    #undef ISSUE
    #undef COMPUTE_KS
}

#define CONV_SMEM (4*STG*4)   // 104448 B -> 2 CTAs/SM

// ===========================================================================
extern "C" void kernel_launch(void* const* d_in, const int* in_sizes, int n_in,
                              void* d_out, int out_size) {
    const float* x       = (const float*)d_in[0];
    const float* experts = (const float*)d_in[1];
    const float* rw1     = (const float*)d_in[2];
    const float* rb1     = (const float*)d_in[3];
    const float* rw2     = (const float*)d_in[4];
    const float* rb2     = (const float*)d_in[5];
    float* out           = (float*)d_out;

    static bool attr_set = false;
    if (!attr_set) {
        cudaFuncSetAttribute(conv_mma_kernel,
                             cudaFuncAttributeMaxDynamicSharedMemorySize, CONV_SMEM);
        attr_set = true;
    }

    pad_pool_kernel<<<dim3(C_, B_), 128>>>(x);
    mlp_kernel<<<B_, 64>>>(rw1, rb1, rw2, rb2);
    combine_kernel<<<dim3(2*NKT, B_), 256>>>(experts);
    conv_mma_kernel<<<dim3(25, 2, B_), 256, CONV_SMEM>>>(out);
}

// round 16
// speedup vs baseline: 1.8556x; 1.1274x over previous
#include <cuda_runtime.h>
#include <cuda_bf16.h>
#include <stdint.h>
#include <math.h>

#define B_   32
#define C_   256
#define HH   56
#define WW   56
#define E_   4
#define O_   256
#define HID_ 64
#define NPIX 3136
#define KDIM 2304
#define WPERB (O_*KDIM)
#define BK   32
#define NKT  (KDIM/BK)                // 72 k-tiles
#define PIMG 3364                     // 58*58 padded plane
#define KROW 136                      // A packed m stride (floats)
#define ASTG (BK*KROW)                // 4352 floats per A stage
#define NSTR 104                      // B smem n stride (floats)
#define BSTG (BK*NSTR)                // 3328 floats per B stage
#define BN   96                       // CTA n tile
#define NTILES 33                     // ceil(3136/96)

// ---------------- device scratch (no runtime allocation) ----------------
__device__ float g_routing[B_*E_];
__device__ float g_pooled[B_*C_];
__device__ int   g_ktab[KDIM];
// A tf32, k-major packed blocks: [b][tile_m(2)][kt(72)] -> [k(32)][m(136 pad)]
__device__ __align__(16) float g_combined[(size_t)B_*2*NKT*ASTG];
__device__ __align__(16) float g_xpad[(size_t)B_*C_*PIMG + 4096]; // padded tf32 x

// ---------------- helpers ----------------
__device__ __forceinline__ uint32_t f2tf32(float f) {
    uint32_t u;
    asm("cvt.rna.tf32.f32 %0, %1;" : "=r"(u) : "f"(f));
    return u;
}

__device__ __forceinline__ void mma_tf32(float* d, const uint32_t* a, uint32_t b0, uint32_t b1) {
    asm volatile(
        "mma.sync.aligned.m16n8k8.row.col.f32.tf32.tf32.f32 "
        "{%0,%1,%2,%3}, {%4,%5,%6,%7}, {%8,%9}, {%0,%1,%2,%3};"
        : "+f"(d[0]), "+f"(d[1]), "+f"(d[2]), "+f"(d[3])
        : "r"(a[0]), "r"(a[1]), "r"(a[2]), "r"(a[3]), "r"(b0), "r"(b1));
}

#define CP_ASYNC16(dst_u32, src_ptr) \
    asm volatile("cp.async.cg.shared.global [%0], [%1], 16;" :: "r"(dst_u32), "l"(src_ptr))
#define CP_ASYNC4(dst_u32, src_ptr) \
    asm volatile("cp.async.ca.shared.global [%0], [%1], 4;" :: "r"(dst_u32), "l"(src_ptr))
#define CP_COMMIT() asm volatile("cp.async.commit_group;" ::: "memory")
#define CP_WAIT0()  asm volatile("cp.async.wait_group 0;"  ::: "memory")

// ===========================================================================
// Kernel 1a: fused zero-pad + tf32-round + global average pool.
// ===========================================================================
__global__ void __launch_bounds__(128) pad_pool_kernel(const float* __restrict__ x) {
    const int c = blockIdx.x, b = blockIdx.y;
    const int tid = threadIdx.x;
    const float* src = x + ((size_t)b*C_ + c)*NPIX;
    float* dst = g_xpad + ((size_t)b*C_ + c)*PIMG;

    float s = 0.f;
    for (int idx = tid; idx < PIMG; idx += 128) {
        const int py = idx / 58;
        const int px = idx - py*58;
        float v = 0.f;
        if ((unsigned)(py-1) < 56u && (unsigned)(px-1) < 56u) {
            v = src[(py-1)*WW + (px-1)];
            s += v;
        }
        dst[idx] = __uint_as_float(f2tf32(v));
    }
    #pragma unroll
    for (int o = 16; o; o >>= 1) s += __shfl_xor_sync(0xffffffffu, s, o);
    __shared__ float ws[4];
    if ((tid & 31) == 0) ws[tid >> 5] = s;
    __syncthreads();
    if (tid == 0) g_pooled[b*C_ + c] = (ws[0]+ws[1]+ws[2]+ws[3]) * (1.0f/(float)NPIX);
}

// ===========================================================================
// Kernel 1b: MLP + softmax routing. grid B_, 64 threads. Block 0 also fills ktab.
// ===========================================================================
__global__ void __launch_bounds__(64) mlp_kernel(const float* __restrict__ rw1,
                                                 const float* __restrict__ rb1,
                                                 const float* __restrict__ rw2,
                                                 const float* __restrict__ rb2) {
    const int b = blockIdx.x, t = threadIdx.x;
    if (b == 0) {
        for (int k = t; k < KDIM; k += 64) {
            int c = k / 9, rem = k - 9*c;
            int ky = rem / 3 - 1, kx = rem % 3 - 1;
            g_ktab[k] = c*PIMG + ky*58 + kx;
        }
    }
    __shared__ float pl[C_];
    __shared__ float hid[HID_];
    __shared__ float logits[E_];
    for (int c = t; c < C_; c += 64) pl[c] = g_pooled[b*C_ + c];
    __syncthreads();
    {
        float s = rb1[t];
        const float* w = rw1 + t * C_;
        #pragma unroll 8
        for (int c = 0; c < C_; c++) s = fmaf(w[c], pl[c], s);
        hid[t] = fmaxf(s, 0.f);
    }
    __syncthreads();
    if (t < E_) {
        float s = rb2[t];
        const float* w = rw2 + t * HID_;
        #pragma unroll 8
        for (int h = 0; h < HID_; h++) s = fmaf(w[h], hid[h], s);
        logits[t] = s;
    }
    __syncthreads();
    if (t == 0) {
        float m = logits[0];
        #pragma unroll
        for (int e = 1; e < E_; e++) m = fmaxf(m, logits[e]);
        float ex[E_], sum = 0.f;
        #pragma unroll
        for (int e = 0; e < E_; e++) { ex[e] = expf(logits[e] - m); sum += ex[e]; }
        float inv = 1.0f / sum;
        #pragma unroll
        for (int e = 0; e < E_; e++) g_routing[b*E_ + e] = ex[e] * inv;
    }
}

// ===========================================================================
// Kernel 2: mix experts -> k-major packed tf32 A blocks [32][136].
//   grid (2*NKT, B_) = (144, 32), 256 threads, smem-staged transpose.
// ===========================================================================
__global__ void __launch_bounds__(256) combine_kernel(const float* __restrict__ experts) {
    __shared__ float st[128*33];
    const int b  = blockIdx.y;
    const int bx = blockIdx.x;                 // tile_m*NKT + kt
    const int tile_m = bx / NKT;
    const int kt = bx - tile_m*NKT;
    const int tid = threadIdx.x;

    const float r0 = g_routing[b*E_+0], r1 = g_routing[b*E_+1];
    const float r2 = g_routing[b*E_+2], r3 = g_routing[b*E_+3];

    // read 128 rows x 32 k: 1024 float4, coalesced (8 float4 per row)
    #pragma unroll
    for (int i = 0; i < 4; i++) {
        const int idx = tid + i*256;
        const int row = idx >> 3, c4 = idx & 7;
        const size_t base = (size_t)(tile_m*128 + row)*KDIM + kt*32 + c4*4;
        float4 a = *(const float4*)(experts + base);
        float4 c = *(const float4*)(experts + (size_t)WPERB   + base);
        float4 d = *(const float4*)(experts + (size_t)2*WPERB + base);
        float4 f = *(const float4*)(experts + (size_t)3*WPERB + base);
        float* dst = st + row*33 + c4*4;
        dst[0] = __uint_as_float(f2tf32(r0*a.x + r1*c.x + r2*d.x + r3*f.x));
        dst[1] = __uint_as_float(f2tf32(r0*a.y + r1*c.y + r2*d.y + r3*f.y));
        dst[2] = __uint_as_float(f2tf32(r0*a.z + r1*c.z + r2*d.z + r3*f.z));
        dst[3] = __uint_as_float(f2tf32(r0*a.w + r1*c.w + r2*d.w + r3*f.w));
    }
    __syncthreads();

    // transpose out: [k][136]; thread: k = tid>>3, m0 = (tid&7)*16 (coalesced)
    float* outp = g_combined + ((size_t)(b*2 + tile_m)*NKT + kt)*ASTG;
    const int k  = tid >> 3;
    const int m0 = (tid & 7) * 16;
    #pragma unroll
    for (int i = 0; i < 4; i++) {
        const float* s = st + (m0 + 4*i)*33 + k;
        float4 v = make_float4(s[0], s[33], s[66], s[99]);
        *(float4*)(outp + k*KROW + m0 + 4*i) = v;
    }
}

// ===========================================================================
// Kernel 3: TF32 mma.sync implicit-GEMM conv.
//   CTA 128(oc) x 96(px), 4 warps = 2(m) x 2(n), warp tile 64x48, 3 CTAs/SM.
//   A: linear cp.async of packed [32][136] blocks.
//   B: cp.async.ca 4B im2col gather -> [k32][n104] smem.
// ===========================================================================
__global__ void __launch_bounds__(128, 3) conv_mma_kernel(float* __restrict__ out) {
    extern __shared__ float sm[];
    float* As = sm;                     // 2 * ASTG
    float* Bs = sm + 2*ASTG;            // 2 * BSTG

    const int tid    = threadIdx.x;
    const int lane   = tid & 31;
    const int warp   = tid >> 5;
    const int nBase  = blockIdx.x * BN;
    const int tile_m = blockIdx.y;
    const int b      = blockIdx.z;

    const int g  = lane >> 2;      // 0..7
    const int tg = lane & 3;       // 0..3
    const int wm = warp >> 1;      // 0..1 (m)
    const int wn = warp & 1;       // 0..1 (n)

    const float* Ab = g_combined + ((size_t)(b*2 + tile_m)*NKT)*ASTG;

    // B producer: threads 0..95 each own one pixel, 32 k gathers per tile
    const int n  = nBase + tid;
    const int ny = n / WW, nx = n - (n / WW) * WW;
    const float* xpb = g_xpad + (size_t)b*C_*PIMG + (ny+1)*58 + (nx+1);

    const uint32_t sb  = (uint32_t)__cvta_generic_to_shared(sm);
    const uint32_t sbB = sb + 2*ASTG*4u;

    // one tile: A linear 17 KB (9 cp.async16/thread) + B (32 cp.async4, tid<96)
    #define ISSUE(kt_, s) do {                                                       \
        const float* _as = Ab + (size_t)(kt_)*ASTG;                                  \
        _Pragma("unroll")                                                            \
        for (int i = 0; i < 9; i++) {                                                \
            int idx = tid + i*128;                                                   \
            if (idx < ASTG/4)                                                        \
                CP_ASYNC16(sb + (uint32_t)((s)*ASTG + idx*4)*4u, _as + idx*4);       \
        }                                                                            \
        if (tid < BN) {                                                              \
            const int4* _t4 = (const int4*)(g_ktab + (kt_)*BK);                      \
            const uint32_t _d0 = sbB + (uint32_t)((s)*BSTG + tid)*4u;                \
            _Pragma("unroll")                                                        \
            for (int qq = 0; qq < 8; qq++) {                                         \
                int4 kv = _t4[qq];                                                   \
                CP_ASYNC4(_d0 + (qq*4+0)*NSTR*4u, xpb + kv.x);                       \
                CP_ASYNC4(_d0 + (qq*4+1)*NSTR*4u, xpb + kv.y);                       \
                CP_ASYNC4(_d0 + (qq*4+2)*NSTR*4u, xpb + kv.z);                       \
                CP_ASYNC4(_d0 + (qq*4+3)*NSTR*4u, xpb + kv.w);                       \
            }                                                                        \
        }                                                                            \
        CP_COMMIT();                                                                 \
    } while (0)

    #define COMPUTE_KS(ks) do {                                                      \
        uint32_t afr[4][4];                                                          \
        _Pragma("unroll")                                                            \
        for (int mi = 0; mi < 4; mi++) {                                             \
            const uint32_t* p = Aw + (ks)*(8*KROW) + mi*16;                          \
            afr[mi][0] = p[0];                                                       \
            afr[mi][1] = p[8];                                                       \
            afr[mi][2] = p[4*KROW];                                                  \
            afr[mi][3] = p[4*KROW + 8];                                              \
        }                                                                            \
        _Pragma("unroll")                                                            \
        for (int ni = 0; ni < 6; ni++) {                                             \
            const uint32_t* q = Bw + (ks)*(8*NSTR) + ni*8;                           \
            uint32_t b0 = q[0], b1 = q[4*NSTR];                                      \
            _Pragma("unroll")                                                        \
            for (int mi = 0; mi < 4; mi++)                                           \
                mma_tf32(acc[mi][ni], afr[mi], b0, b1);                              \
        }                                                                            \
    } while (0)

    float acc[4][6][4];
    #pragma unroll
    for (int mi = 0; mi < 4; mi++)
        #pragma unroll
        for (int ni = 0; ni < 6; ni++)
            #pragma unroll
            for (int qq = 0; qq < 4; qq++) acc[mi][ni][qq] = 0.f;

    // ---- prologue ----
    ISSUE(0, 0);
    CP_WAIT0();
    __syncthreads();

    for (int kt = 0; kt < NKT; kt++) {
        const int cur = kt & 1;
        if (kt + 1 < NKT) ISSUE(kt + 1, cur ^ 1);

        const uint32_t* Aw = (const uint32_t*)(As + cur*ASTG + tg*KROW + wm*64 + g);
        const uint32_t* Bw = (const uint32_t*)(Bs + cur*BSTG + tg*NSTR + wn*48 + g);

        COMPUTE_KS(0);
        COMPUTE_KS(1);
        COMPUTE_KS(2);
        COMPUTE_KS(3);

        if (kt + 1 < NKT) {
            CP_WAIT0();
            __syncthreads();
        }
    }

    // ---- epilogue ----
    float* ob = out + (size_t)b * O_ * NPIX;
    #pragma unroll
    for (int mi = 0; mi < 4; mi++) {
        const int r0 = tile_m*128 + wm*64 + mi*16 + g;
        #pragma unroll
        for (int ni = 0; ni < 6; ni++) {
            const int cb = nBase + wn*48 + ni*8 + 2*tg;
            if (cb < NPIX) {
                *(float2*)(ob + (size_t)r0*NPIX + cb)     = make_float2(acc[mi][ni][0], acc[mi][ni][1]);
                *(float2*)(ob + (size_t)(r0+8)*NPIX + cb) = make_float2(acc[mi][ni][2], acc[mi][ni][3]);
            }
        }
    }
    #undef ISSUE
    #undef COMPUTE_KS
}

#define CONV_SMEM ((2*ASTG + 2*BSTG)*4)   // (8704+6656)*4 = 61440 B -> 3 CTAs/SM

// ===========================================================================
extern "C" void kernel_launch(void* const* d_in, const int* in_sizes, int n_in,
                              void* d_out, int out_size) {
    const float* x       = (const float*)d_in[0];
    const float* experts = (const float*)d_in[1];
    const float* rw1     = (const float*)d_in[2];
    const float* rb1     = (const float*)d_in[3];
    const float* rw2     = (const float*)d_in[4];
    const float* rb2     = (const float*)d_in[5];
    float* out           = (float*)d_out;

    static bool attr_set = false;
    if (!attr_set) {
        cudaFuncSetAttribute(conv_mma_kernel,
                             cudaFuncAttributeMaxDynamicSharedMemorySize, CONV_SMEM);
        attr_set = true;
    }

    pad_pool_kernel<<<dim3(C_, B_), 128>>>(x);
    mlp_kernel<<<B_, 64>>>(rw1, rb1, rw2, rb2);
    combine_kernel<<<dim3(2*NKT, B_), 256>>>(experts);
    conv_mma_kernel<<<dim3(NTILES, 2, B_), 128, CONV_SMEM>>>(out);
}